// round 15
// baseline (speedup 1.0000x reference)
#include <cuda_runtime.h>
#include <math.h>
#include <stdint.h>

#define BATCH 65536
#define UNITS 256
#define KTOT  512
#define TILE_M 64
#define BK 64
#define NSTAGE 8
#define NBLK (BATCH/TILE_M)        // 1024

#define ABUF_BYTES (TILE_M*32*4)                 // 8192
#define BBUF_BYTES 32768                         // BK=64 x 256 x 2B
#define STATS_OFF  (2*ABUF_BYTES + 2*BBUF_BYTES) // 81920
#define SMEM_BYTES (STATS_OFF + TILE_M*16)       // 82944
#define GSTRIDE 260                              // Gbuf row stride (words)

// Pre-baked bf16 weights: [q=0..31][ntpg][g][t4] uint4 (see R13 derivation)
__device__ __align__(16) uint4 g_Bt[32*16*8*4];

// ---------------- helpers ----------------
__device__ __forceinline__ uint32_t smaddr(const void* p){
    uint32_t a;
    asm("{ .reg .u64 t; cvta.to.shared.u64 t, %1; cvt.u32.u64 %0, t; }" : "=r"(a) : "l"(p));
    return a;
}
__device__ __forceinline__ uint32_t pkbf(float lo, float hi){
    uint32_t d;
    asm("cvt.rn.bf16x2.f32 %0, %1, %2;" : "=r"(d) : "f"(hi), "f"(lo));
    return d;
}
__device__ __forceinline__ void cp16(uint32_t d, const void* s){
    asm volatile("cp.async.cg.shared.global [%0], [%1], 16;" :: "r"(d), "l"(s));
}
__device__ __forceinline__ uint2 lds64(uint32_t a){
    uint2 v;
    asm volatile("ld.shared.v2.b32 {%0,%1}, [%2];" : "=r"(v.x), "=r"(v.y) : "r"(a));
    return v;
}
__device__ __forceinline__ uint4 lds128(uint32_t a){
    uint4 v;
    asm volatile("ld.shared.v4.b32 {%0,%1,%2,%3}, [%4];"
        : "=r"(v.x), "=r"(v.y), "=r"(v.z), "=r"(v.w) : "r"(a));
    return v;
}
__device__ __forceinline__ void sts128(uint32_t a, uint32_t v0, uint32_t v1, uint32_t v2, uint32_t v3){
    asm volatile("st.shared.v4.b32 [%0], {%1,%2,%3,%4};"
        :: "r"(a), "r"(v0), "r"(v1), "r"(v2), "r"(v3));
}
__device__ __forceinline__ float tanh_fast(float x){
    float y; asm("tanh.approx.f32 %0, %1;" : "=f"(y) : "f"(x)); return y;
}
__device__ __forceinline__ void mma_bf16(float* d, uint2 a, uint2 a8, uint32_t b0, uint32_t b1){
    asm("mma.sync.aligned.m16n8k16.row.col.f32.bf16.bf16.f32 "
        "{%0,%1,%2,%3}, {%4,%5,%6,%7}, {%8,%9}, {%0,%1,%2,%3};"
        : "+f"(d[0]), "+f"(d[1]), "+f"(d[2]), "+f"(d[3])
        : "r"(a.x), "r"(a8.x), "r"(a.y), "r"(a8.y), "r"(b0), "r"(b1));
}

// ---------------- prep: bf16-convert + fragment-pack weights ----------------
__global__ void prep_B(const float* __restrict__ w_in, const float* __restrict__ w_rec){
    int t = blockIdx.x * 256 + threadIdx.x;
    int t4   = t & 3;
    int g    = (t >> 2) & 7;
    int ntpg = (t >> 5) & 15;
    int q    = t >> 9;
    int kb = q*16;
    int nA = ntpg*16 + g, nB = nA + 8;
    auto Wrow = [&](int k){
        return (k < 256) ? (w_in + (size_t)k*UNITS) : (w_rec + (size_t)(k-256)*UNITS);
    };
    const float* r0 = Wrow(kb + 2*t4);
    const float* r1 = Wrow(kb + 2*t4 + 1);
    const float* r2 = Wrow(kb + 2*t4 + 8);
    const float* r3 = Wrow(kb + 2*t4 + 9);
    uint4 o;
    o.x = pkbf(r0[nA], r1[nA]);
    o.y = pkbf(r2[nA], r3[nA]);
    o.z = pkbf(r0[nB], r1[nB]);
    o.w = pkbf(r2[nB], r3[nB]);
    g_Bt[t] = o;
}

// ---------------- main fused kernel ----------------
__global__ __launch_bounds__(256, 2)
void jfc_main(const float* __restrict__ inputs,
              const float* __restrict__ prev_h,
              const float* __restrict__ prev_G,
              const float* __restrict__ prev_phase,
              const float* __restrict__ bias,
              float* __restrict__ out_h,
              float* __restrict__ out_G,
              float* __restrict__ out_phase)
{
    extern __shared__ __align__(16) char smem[];
    const uint32_t base = smaddr(smem);
    const uint32_t sA0 = base;
    const uint32_t sA1 = base + ABUF_BYTES;
    const uint32_t sB0 = base + 2*ABUF_BYTES;
    const uint32_t sB1 = sB0 + BBUF_BYTES;
    float4* stats = (float4*)(smem + STATS_OFF);
    float*  Gbuf  = (float*)smem;                 // overlays A/B after mainloop (66.5KB)

    const int tid  = threadIdx.x;
    const int lane = tid & 31, wid = tid >> 5;
    const int g  = lane >> 2, t4 = lane & 3;
    const int m0w = (wid >> 2) * 32;
    const int n0w = (wid & 3) * 64;
    const int rowBase = blockIdx.x * TILE_M;

    const int m_l = tid >> 2;       // A loader row
    const int c_l = tid & 3;        // A loader k16-chunk

    float acc[2][8][4];
    #pragma unroll
    for (int a = 0; a < 2; a++)
        #pragma unroll
        for (int b = 0; b < 8; b++)
            #pragma unroll
            for (int c = 0; c < 4; c++) acc[a][b][c] = 0.0f;

    float4 av0, av1, av2, av3;

    const uint32_t aRowOff = (uint32_t)(rowBase + m_l)*UNITS + c_l*16;

    // load av for stage s (inputs streamed once: ldcs; prev_h cached: re-read later)
    auto loadAV = [&](int s){
        if (s < 4) {
            const float* p = inputs + aRowOff + (s & 3)*BK;
            av0 = __ldcs((const float4*)p);
            av1 = __ldcs((const float4*)(p + 4));
            av2 = __ldcs((const float4*)(p + 8));
            av3 = __ldcs((const float4*)(p + 12));
        } else {
            const float* p = prev_h + aRowOff + (s & 3)*BK;
            av0 = *(const float4*)p;
            av1 = *(const float4*)(p + 4);
            av2 = *(const float4*)(p + 8);
            av3 = *(const float4*)(p + 12);
        }
    };

    // XOR swizzle f(m) = 8*(m&3) ^ 4*(m&1); 2x STS.128, conflict-free (R14-derived)
    const int fA = 8*(m_l & 3) ^ 4*(m_l & 1);
    auto storeA = [&](uint32_t sdst){
        const int pb = 8*c_l;
        const uint32_t rb = sdst + m_l*128;
        const uint32_t b1 = rb + ((pb ^ fA) << 2);
        const uint32_t b2 = b1 ^ 16;
        sts128(b1, pkbf(av0.x, av0.y), pkbf(av2.x, av2.y),
                   pkbf(av0.z, av0.w), pkbf(av2.z, av2.w));
        sts128(b2, pkbf(av1.x, av1.y), pkbf(av3.x, av3.y),
                   pkbf(av1.z, av1.w), pkbf(av3.z, av3.w));
    };

    // ---- prologue: stage 0 in SMEM, av preloaded for stage 1 ----
    {
        loadAV(0);
        const char* bsrc = (const char*)g_Bt;
        #pragma unroll
        for (int i = 0; i < 8; i++) cp16(sB0 + (tid + 256*i)*16, bsrc + (size_t)(tid + 256*i)*16);
        asm volatile("cp.async.commit_group;");
        storeA(sA0);
        loadAV(1);
        asm volatile("cp.async.wait_group 0;");
        __syncthreads();
    }

    const int swg = 8*(g & 3) ^ 4*(g & 1);
    const uint32_t bwoff = (uint32_t)((wid & 3)*2048 + g*64 + t4*16);

    // ---- mainloop: 8 stages of BK=64; A stored at stage START (STS drains under compute) ----
    for (int s = 0; s < NSTAGE; s++) {
        const int pp = s & 1;
        const uint32_t sAc = pp ? sA1 : sA0;
        const uint32_t sBc = pp ? sB1 : sB0;
        const uint32_t sAn = pp ? sA0 : sA1;
        const uint32_t sBn = pp ? sB0 : sB1;

        if (s + 1 < NSTAGE) {
            const char* bsrc = (const char*)g_Bt + (size_t)(s + 1) * BBUF_BYTES;
            #pragma unroll
            for (int i = 0; i < 8; i++) cp16(sBn + (tid + 256*i)*16, bsrc + (size_t)(tid + 256*i)*16);
            asm volatile("cp.async.commit_group;");
            storeA(sAn);            // av holds stage s+1 data (loaded at s-1)
        }
        if (s + 2 < NSTAGE) loadAV(s + 2);

        // compute 4 k16-steps
        #pragma unroll
        for (int kc = 0; kc < 4; kc++) {
            uint4 bq[4];
            const uint32_t bb = sBc + kc*8192 + bwoff;
            #pragma unroll
            for (int ntp = 0; ntp < 4; ntp++) bq[ntp] = lds128(bb + ntp*512);

            const uint32_t acol = (uint32_t)((kc*8 + 2*t4) ^ swg);
            uint2 arg[2], arg8[2];
            #pragma unroll
            for (int mt = 0; mt < 2; mt++) {
                uint32_t aa = sAc + (((m0w + mt*16 + g)*32 + acol))*4;
                arg[mt]  = lds64(aa);
                arg8[mt] = lds64(aa + 1024);
            }
            #pragma unroll
            for (int mt = 0; mt < 2; mt++)
                #pragma unroll
                for (int ntp = 0; ntp < 4; ntp++) {
                    mma_bf16(acc[mt][2*ntp+0], arg[mt], arg8[mt], bq[ntp].x, bq[ntp].y);
                    mma_bf16(acc[mt][2*ntp+1], arg[mt], arg8[mt], bq[ntp].z, bq[ntp].w);
                }
        }

        if (s + 1 < NSTAGE) asm volatile("cp.async.wait_group 0;");
        __syncthreads();
    }

    // ---- epilogue phase 1: per-row stats (32-bit offsets, streaming hints) ----
    const float inv_units = 1.0f / 256.0f;
    const float dphase = 0.2513274122871834f;
    #pragma unroll
    for (int i = 0; i < 8; i++) {
        const int r = wid*8 + i;
        const uint32_t rowOff = (uint32_t)(rowBase + r) * UNITS;
        float sG = 0.f, sG2 = 0.f, sR = 0.f;
        #pragma unroll
        for (int j = 0; j < 8; j++) {
            int c = lane + 32*j;
            float raw = prev_h[rowOff + (c ^ 128)];
            float pg  = __ldcs(&prev_G[rowOff + c]);
            float gv  = 0.9f*pg + 0.1f*raw;
            __stcs(&out_G[rowOff + c], gv);
            Gbuf[r*GSTRIDE + c] = gv;
            sG += gv; sG2 += gv*gv; sR += raw;
        }
        #pragma unroll
        for (int off = 16; off; off >>= 1) {
            sG  += __shfl_xor_sync(0xffffffffu, sG,  off);
            sG2 += __shfl_xor_sync(0xffffffffu, sG2, off);
            sR  += __shfl_xor_sync(0xffffffffu, sR,  off);
        }
        float mean = sG * inv_units;
        float var  = fmaxf(sG2 * inv_units - mean*mean, 0.0f);
        float invd = 1.0f / (sqrtf(var) + 1e-6f);
        float nphase = prev_phase[rowBase + r] + dphase;
        float cf = 0.5f * (__sinf(nphase) + 0.05f * (sR * inv_units - 0.1f));
        if (lane == 0) {
            stats[r] = make_float4(mean, invd, cf, 0.0f);
            out_phase[rowBase + r] = nphase;
        }
    }
    __syncthreads();

    // ---- epilogue phase 2: pointwise from register accumulators ----
    #pragma unroll
    for (int mt = 0; mt < 2; mt++) {
        const int lm1 = m0w + mt*16 + g;
        const int lm2 = lm1 + 8;
        const float4 s1 = stats[lm1];
        const float4 s2 = stats[lm2];
        const uint32_t ro1 = (uint32_t)(rowBase + lm1) * UNITS;
        const uint32_t ro2 = (uint32_t)(rowBase + lm2) * UNITS;
        #pragma unroll
        for (int nt = 0; nt < 8; nt++) {
            const int cA = n0w + nt*8 + 2*t4;
            const float2 bs = *(const float2*)&bias[cA];
            #pragma unroll
            for (int half = 0; half < 2; half++) {
                const float4 st   = half ? s2  : s1;
                const uint32_t ro = half ? ro2 : ro1;
                const int    lm   = half ? lm2 : lm1;
                const float z0    = acc[mt][nt][half*2 + 0];
                const float z1    = acc[mt][nt][half*2 + 1];
                const float2 gg   = *(const float2*)&Gbuf[lm*GSTRIDE + cA];
                const float2 ph   = *(const float2*)&prev_h[ro + cA];
                float f0 = 1.0f + st.z * tanh_fast((gg.x - st.x) * st.y);
                float f1 = 1.0f + st.z * tanh_fast((gg.y - st.x) * st.y);
                float zz0 = (z0 + bs.x) * f0;
                float zz1 = (z1 + bs.y) * f1;
                float e0 = (zz0 > 0.0f) ? zz0 : (__expf(zz0) - 1.0f);
                float e1 = (zz1 > 0.0f) ? zz1 : (__expf(zz1) - 1.0f);
                float h0 = 0.9f*ph.x + 0.1f*e0;
                float h1 = 0.9f*ph.y + 0.1f*e1;
                h0 = fminf(fmaxf(h0, -20.0f), 20.0f);
                h1 = fminf(fmaxf(h1, -20.0f), 20.0f);
                __stcs((float2*)&out_h[ro + cA], make_float2(h0, h1));
            }
        }
    }
}

extern "C" void kernel_launch(void* const* d_in, const int* in_sizes, int n_in,
                              void* d_out, int out_size) {
    const float* inputs     = (const float*)d_in[0];
    const float* prev_h     = (const float*)d_in[1];
    const float* prev_G     = (const float*)d_in[2];
    const float* prev_phase = (const float*)d_in[3];
    const float* w_in       = (const float*)d_in[4];
    const float* w_rec      = (const float*)d_in[5];
    const float* bias       = (const float*)d_in[6];

    float* out   = (float*)d_out;
    float* out_h = out;
    float* out_G = out + (size_t)BATCH * UNITS;
    float* out_p = out + 2 * (size_t)BATCH * UNITS;

    cudaFuncSetAttribute(jfc_main, cudaFuncAttributeMaxDynamicSharedMemorySize, SMEM_BYTES);

    prep_B<<<64, 256>>>(w_in, w_rec);
    jfc_main<<<NBLK, 256, SMEM_BYTES>>>(inputs, prev_h, prev_G, prev_phase, bias,
                                        out_h, out_G, out_p);
}

// round 16
// speedup vs baseline: 1.7842x; 1.7842x over previous
#include <cuda_runtime.h>
#include <math.h>
#include <stdint.h>

#define BATCH 65536
#define UNITS 256
#define KTOT  512
#define TILE_M 64
#define BK 64
#define NSTAGE 8
#define NBLK (BATCH/TILE_M)        // 1024

#define ABUF_BYTES (TILE_M*32*4)                 // 8192
#define BBUF_BYTES 32768                         // BK=64 x 256 x 2B
#define STATS_OFF  (2*ABUF_BYTES + 2*BBUF_BYTES) // 81920
#define SMEM_BYTES (STATS_OFF + TILE_M*16)       // 82944
#define GSTRIDE 260                              // Gbuf row stride (words)

// Pre-baked bf16 weights: [q=0..31][ntpg][g][t4] uint4 (see R13 derivation)
__device__ __align__(16) uint4 g_Bt[32*16*8*4];

// ---------------- helpers ----------------
__device__ __forceinline__ uint32_t smaddr(const void* p){
    uint32_t a;
    asm("{ .reg .u64 t; cvta.to.shared.u64 t, %1; cvt.u32.u64 %0, t; }" : "=r"(a) : "l"(p));
    return a;
}
__device__ __forceinline__ uint32_t pkbf(float lo, float hi){
    uint32_t d;
    asm("cvt.rn.bf16x2.f32 %0, %1, %2;" : "=r"(d) : "f"(hi), "f"(lo));  // hi->upper, lo->lower
    return d;
}
__device__ __forceinline__ void cp16(uint32_t d, const void* s){
    asm volatile("cp.async.cg.shared.global [%0], [%1], 16;" :: "r"(d), "l"(s));
}
__device__ __forceinline__ uint2 lds64(uint32_t a){
    uint2 v;
    asm volatile("ld.shared.v2.b32 {%0,%1}, [%2];" : "=r"(v.x), "=r"(v.y) : "r"(a));
    return v;
}
__device__ __forceinline__ uint4 lds128(uint32_t a){
    uint4 v;
    asm volatile("ld.shared.v4.b32 {%0,%1,%2,%3}, [%4];"
        : "=r"(v.x), "=r"(v.y), "=r"(v.z), "=r"(v.w) : "r"(a));
    return v;
}
__device__ __forceinline__ void sts128(uint32_t a, uint32_t v0, uint32_t v1, uint32_t v2, uint32_t v3){
    asm volatile("st.shared.v4.b32 [%0], {%1,%2,%3,%4};"
        :: "r"(a), "r"(v0), "r"(v1), "r"(v2), "r"(v3));
}
__device__ __forceinline__ float tanh_fast(float x){
    float y; asm("tanh.approx.f32 %0, %1;" : "=f"(y) : "f"(x)); return y;
}
// bf16 m16n8k16: a0=(g,k) a1=(g+8,k) a2=(g,k+8) a3=(g+8,k+8); each reg = bf16x2 (lo=lower k)
__device__ __forceinline__ void mma_bf16(float* d, uint2 a, uint2 a8, uint32_t b0, uint32_t b1){
    asm("mma.sync.aligned.m16n8k16.row.col.f32.bf16.bf16.f32 "
        "{%0,%1,%2,%3}, {%4,%5,%6,%7}, {%8,%9}, {%0,%1,%2,%3};"
        : "+f"(d[0]), "+f"(d[1]), "+f"(d[2]), "+f"(d[3])
        : "r"(a.x), "r"(a8.x), "r"(a.y), "r"(a8.y), "r"(b0), "r"(b1));
}

// ---------------- prep: bf16-convert + fragment-pack weights ----------------
__global__ void prep_B(const float* __restrict__ w_in, const float* __restrict__ w_rec){
    int t = blockIdx.x * 256 + threadIdx.x;
    int t4   = t & 3;
    int g    = (t >> 2) & 7;
    int ntpg = (t >> 5) & 15;
    int q    = t >> 9;
    int kb = q*16;
    int nA = ntpg*16 + g, nB = nA + 8;
    auto Wrow = [&](int k){
        return (k < 256) ? (w_in + (size_t)k*UNITS) : (w_rec + (size_t)(k-256)*UNITS);
    };
    const float* r0 = Wrow(kb + 2*t4);
    const float* r1 = Wrow(kb + 2*t4 + 1);
    const float* r2 = Wrow(kb + 2*t4 + 8);
    const float* r3 = Wrow(kb + 2*t4 + 9);
    uint4 o;
    o.x = pkbf(r0[nA], r1[nA]);
    o.y = pkbf(r2[nA], r3[nA]);
    o.z = pkbf(r0[nB], r1[nB]);
    o.w = pkbf(r2[nB], r3[nB]);
    g_Bt[t] = o;
}

// ---------------- main fused kernel: 256 thr, 2 CTAs/SM, bf16 MMA, BK=64 ----------------
__global__ __launch_bounds__(256, 2)
void jfc_main(const float* __restrict__ inputs,
              const float* __restrict__ prev_h,
              const float* __restrict__ prev_G,
              const float* __restrict__ prev_phase,
              const float* __restrict__ bias,
              float* __restrict__ out_h,
              float* __restrict__ out_G,
              float* __restrict__ out_phase)
{
    extern __shared__ __align__(16) char smem[];
    const uint32_t base = smaddr(smem);
    const uint32_t sA0 = base;
    const uint32_t sA1 = base + ABUF_BYTES;
    const uint32_t sB0 = base + 2*ABUF_BYTES;
    const uint32_t sB1 = sB0 + BBUF_BYTES;
    float4* stats = (float4*)(smem + STATS_OFF);
    float*  Gbuf  = (float*)smem;                 // overlays A/B after mainloop (66.5KB)

    const int tid  = threadIdx.x;
    const int lane = tid & 31, wid = tid >> 5;
    const int g  = lane >> 2, t4 = lane & 3;
    const int m0w = (wid >> 2) * 32;
    const int n0w = (wid & 3) * 64;
    const int rowBase = blockIdx.x * TILE_M;

    const int m_l = tid >> 2;       // A loader row
    const int c_l = tid & 3;        // A loader k16-chunk

    float acc[2][8][4];
    #pragma unroll
    for (int a = 0; a < 2; a++)
        #pragma unroll
        for (int b = 0; b < 8; b++)
            #pragma unroll
            for (int c = 0; c < 4; c++) acc[a][b][c] = 0.0f;

    float4 av0, av1, av2, av3;

    // XOR swizzle: f(m) = 8*(m&3) ^ 4*(m&1); positions pb..pb+7 -> two aligned 4-word blocks
    const int fA = 8*(m_l & 3) ^ 4*(m_l & 1);
    auto storeA = [&](uint32_t sdst){
        const int pb = 8*c_l;
        const uint32_t rb = sdst + m_l*128;              // 32 words/row
        const uint32_t b1 = rb + ((pb ^ fA) << 2);
        const uint32_t b2 = b1 ^ 16;                     // (pb+4)^fA block
        sts128(b1, pkbf(av0.x, av0.y), pkbf(av2.x, av2.y),
                   pkbf(av0.z, av0.w), pkbf(av2.z, av2.w));
        sts128(b2, pkbf(av1.x, av1.y), pkbf(av3.x, av3.y),
                   pkbf(av1.z, av1.w), pkbf(av3.z, av3.w));
    };

    // ---- prologue: stage 0 ----
    {
        const float* src = inputs + (size_t)(rowBase + m_l)*UNITS + c_l*16;
        av0 = *(const float4*)src;
        av1 = *(const float4*)(src + 4);
        av2 = *(const float4*)(src + 8);
        av3 = *(const float4*)(src + 12);
        const char* bsrc = (const char*)g_Bt;
        #pragma unroll
        for (int i = 0; i < 8; i++) cp16(sB0 + (tid + 256*i)*16, bsrc + (size_t)(tid + 256*i)*16);
        asm volatile("cp.async.commit_group;");
        storeA(sA0);
        asm volatile("cp.async.wait_group 0;");
        __syncthreads();
    }

    const int swg = 8*(g & 3) ^ 4*(g & 1);                 // A fragment swizzle (same f)
    const uint32_t bwoff = (uint32_t)((wid & 3)*2048 + g*64 + t4*16);  // B lane offset per q-block

    // ---- mainloop: 8 stages of BK=64, double-buffered (R14 schedule, known good) ----
    for (int s = 0; s < NSTAGE; s++) {
        const int pp = s & 1;
        const uint32_t sAc = pp ? sA1 : sA0;
        const uint32_t sBc = pp ? sB1 : sB0;
        const uint32_t sAn = pp ? sA0 : sA1;
        const uint32_t sBn = pp ? sB0 : sB1;

        if (s + 1 < NSTAGE) {
            const int s1 = s + 1;
            const float* srcb = ((s1 < 4) ? inputs : prev_h)
                              + (size_t)(rowBase + m_l)*UNITS + (s1 & 3)*BK + c_l*16;
            av0 = *(const float4*)srcb;
            av1 = *(const float4*)(srcb + 4);
            av2 = *(const float4*)(srcb + 8);
            av3 = *(const float4*)(srcb + 12);
            const char* bsrc = (const char*)g_Bt + (size_t)s1 * BBUF_BYTES;
            #pragma unroll
            for (int i = 0; i < 8; i++) cp16(sBn + (tid + 256*i)*16, bsrc + (size_t)(tid + 256*i)*16);
            asm volatile("cp.async.commit_group;");
        }

        // compute 4 k16-steps on current buffers
        #pragma unroll
        for (int kc = 0; kc < 4; kc++) {
            uint4 bq[4];
            const uint32_t bb = sBc + kc*8192 + bwoff;
            #pragma unroll
            for (int ntp = 0; ntp < 4; ntp++) bq[ntp] = lds128(bb + ntp*512);

            const uint32_t acol = (uint32_t)((kc*8 + 2*t4) ^ swg);
            uint2 arg[2], arg8[2];
            #pragma unroll
            for (int mt = 0; mt < 2; mt++) {
                uint32_t aa = sAc + (((m0w + mt*16 + g)*32 + acol))*4;
                arg[mt]  = lds64(aa);           // {a0, a2}  (row g)
                arg8[mt] = lds64(aa + 1024);    // {a1, a3}  (row g+8)
            }
            #pragma unroll
            for (int mt = 0; mt < 2; mt++)
                #pragma unroll
                for (int ntp = 0; ntp < 4; ntp++) {
                    mma_bf16(acc[mt][2*ntp+0], arg[mt], arg8[mt], bq[ntp].x, bq[ntp].y);
                    mma_bf16(acc[mt][2*ntp+1], arg[mt], arg8[mt], bq[ntp].z, bq[ntp].w);
                }
        }

        if (s + 1 < NSTAGE) {
            storeA(sAn);
            asm volatile("cp.async.wait_group 0;");
        }
        __syncthreads();
    }

    // ---- epilogue phase 1: per-row stats (32-bit offsets, Gbuf cache) ----
    const float inv_units = 1.0f / 256.0f;
    const float dphase = 0.2513274122871834f;
    #pragma unroll
    for (int i = 0; i < 8; i++) {
        const int r = wid*8 + i;
        const uint32_t rowOff = (uint32_t)(rowBase + r) * UNITS;
        float sG = 0.f, sG2 = 0.f, sR = 0.f;
        #pragma unroll
        for (int j = 0; j < 8; j++) {
            int c = lane + 32*j;
            float raw = prev_h[rowOff + (c ^ 128)];
            float pg  = prev_G[rowOff + c];
            float gv  = 0.9f*pg + 0.1f*raw;
            out_G[rowOff + c] = gv;
            Gbuf[r*GSTRIDE + c] = gv;
            sG += gv; sG2 += gv*gv; sR += raw;
        }
        #pragma unroll
        for (int off = 16; off; off >>= 1) {
            sG  += __shfl_xor_sync(0xffffffffu, sG,  off);
            sG2 += __shfl_xor_sync(0xffffffffu, sG2, off);
            sR  += __shfl_xor_sync(0xffffffffu, sR,  off);
        }
        float mean = sG * inv_units;
        float var  = fmaxf(sG2 * inv_units - mean*mean, 0.0f);
        float invd = 1.0f / (sqrtf(var) + 1e-6f);
        float nphase = prev_phase[rowBase + r] + dphase;
        float cf = 0.5f * (__sinf(nphase) + 0.05f * (sR * inv_units - 0.1f));
        if (lane == 0) {
            stats[r] = make_float4(mean, invd, cf, 0.0f);
            out_phase[rowBase + r] = nphase;
        }
    }
    __syncthreads();

    // ---- epilogue phase 2: pointwise from register accumulators ----
    #pragma unroll
    for (int mt = 0; mt < 2; mt++) {
        const int lm1 = m0w + mt*16 + g;
        const int lm2 = lm1 + 8;
        const float4 s1 = stats[lm1];
        const float4 s2 = stats[lm2];
        const uint32_t ro1 = (uint32_t)(rowBase + lm1) * UNITS;
        const uint32_t ro2 = (uint32_t)(rowBase + lm2) * UNITS;
        #pragma unroll
        for (int nt = 0; nt < 8; nt++) {
            const int cA = n0w + nt*8 + 2*t4;
            const float2 bs = *(const float2*)&bias[cA];
            #pragma unroll
            for (int half = 0; half < 2; half++) {
                const float4 st   = half ? s2  : s1;
                const uint32_t ro = half ? ro2 : ro1;
                const int    lm   = half ? lm2 : lm1;
                const float z0    = acc[mt][nt][half*2 + 0];
                const float z1    = acc[mt][nt][half*2 + 1];
                const float2 gg   = *(const float2*)&Gbuf[lm*GSTRIDE + cA];
                const float2 ph   = *(const float2*)&prev_h[ro + cA];
                float f0 = 1.0f + st.z * tanh_fast((gg.x - st.x) * st.y);
                float f1 = 1.0f + st.z * tanh_fast((gg.y - st.x) * st.y);
                float zz0 = (z0 + bs.x) * f0;
                float zz1 = (z1 + bs.y) * f1;
                float e0 = (zz0 > 0.0f) ? zz0 : (__expf(zz0) - 1.0f);
                float e1 = (zz1 > 0.0f) ? zz1 : (__expf(zz1) - 1.0f);
                float h0 = 0.9f*ph.x + 0.1f*e0;
                float h1 = 0.9f*ph.y + 0.1f*e1;
                h0 = fminf(fmaxf(h0, -20.0f), 20.0f);
                h1 = fminf(fmaxf(h1, -20.0f), 20.0f);
                *(float2*)&out_h[ro + cA] = make_float2(h0, h1);
            }
        }
    }
}

extern "C" void kernel_launch(void* const* d_in, const int* in_sizes, int n_in,
                              void* d_out, int out_size) {
    const float* inputs     = (const float*)d_in[0];
    const float* prev_h     = (const float*)d_in[1];
    const float* prev_G     = (const float*)d_in[2];
    const float* prev_phase = (const float*)d_in[3];
    const float* w_in       = (const float*)d_in[4];
    const float* w_rec      = (const float*)d_in[5];
    const float* bias       = (const float*)d_in[6];

    float* out   = (float*)d_out;
    float* out_h = out;
    float* out_G = out + (size_t)BATCH * UNITS;
    float* out_p = out + 2 * (size_t)BATCH * UNITS;

    cudaFuncSetAttribute(jfc_main, cudaFuncAttributeMaxDynamicSharedMemorySize, SMEM_BYTES);

    prep_B<<<64, 256>>>(w_in, w_rec);
    jfc_main<<<NBLK, 256, SMEM_BYTES>>>(inputs, prev_h, prev_G, prev_phase, bias,
                                        out_h, out_G, out_p);
}